// round 3
// baseline (speedup 1.0000x reference)
#include <cuda_runtime.h>
#include <cuda_bf16.h>
#include <stdint.h>

#define N_TOK 16384
#define D_DIM 2048
#define H_DIM 1024
#define N_EXP 16

// ------------------------- scratch (device globals; no allocs) -------------
__device__ __nv_bfloat16 g_xh[(size_t)N_TOK * D_DIM];
__device__ __nv_bfloat16 g_xl[(size_t)N_TOK * D_DIM];
__device__ __nv_bfloat16 g_w1h[(size_t)N_EXP * 2 * H_DIM * D_DIM];
__device__ __nv_bfloat16 g_w1l[(size_t)N_EXP * 2 * H_DIM * D_DIM];
__device__ __nv_bfloat16 g_w2th[(size_t)N_EXP * D_DIM * H_DIM];
__device__ __nv_bfloat16 g_w2tl[(size_t)N_EXP * D_DIM * H_DIM];
__device__ float g_upgate[(size_t)N_TOK * 2 * H_DIM];
__device__ __nv_bfloat16 g_hh[(size_t)N_TOK * H_DIM];
__device__ __nv_bfloat16 g_hl[(size_t)N_TOK * H_DIM];

// ------------------------- PTX helpers (compute_103-legal only) ------------
__device__ __forceinline__ uint32_t smem_u32(const void* p) {
    uint32_t a;
    asm("{ .reg .u64 t; cvta.to.shared.u64 t, %1; cvt.u32.u64 %0, t; }"
        : "=r"(a) : "l"(p));
    return a;
}

__device__ __forceinline__ void cp16(uint32_t dst, const void* src) {
    asm volatile("cp.async.cg.shared.global [%0], [%1], 16;\n"
                 :: "r"(dst), "l"(src));
}
__device__ __forceinline__ void cp_commit() {
    asm volatile("cp.async.commit_group;\n" ::: "memory");
}
template <int NN>
__device__ __forceinline__ void cp_wait() {
    asm volatile("cp.async.wait_group %0;\n" :: "n"(NN) : "memory");
}

__device__ __forceinline__ void ldsm4(uint32_t& r0, uint32_t& r1, uint32_t& r2,
                                      uint32_t& r3, uint32_t addr) {
    asm volatile("ldmatrix.sync.aligned.m8n8.x4.shared.b16 {%0,%1,%2,%3}, [%4];"
                 : "=r"(r0), "=r"(r1), "=r"(r2), "=r"(r3) : "r"(addr));
}

__device__ __forceinline__ void mma16816(float* c, uint32_t a0, uint32_t a1,
                                         uint32_t a2, uint32_t a3, uint32_t b0,
                                         uint32_t b1) {
    asm volatile(
        "mma.sync.aligned.m16n8k16.row.col.f32.bf16.bf16.f32 "
        "{%0,%1,%2,%3}, {%4,%5,%6,%7}, {%8,%9}, {%0,%1,%2,%3};"
        : "+f"(c[0]), "+f"(c[1]), "+f"(c[2]), "+f"(c[3])
        : "r"(a0), "r"(a1), "r"(a2), "r"(a3), "r"(b0), "r"(b1));
}

// ------------------------- pre-pass kernels --------------------------------
__global__ void __launch_bounds__(256) split_kernel(
    const float* __restrict__ src, __nv_bfloat16* __restrict__ hi,
    __nv_bfloat16* __restrict__ lo) {
    size_t i = (size_t)blockIdx.x * blockDim.x + threadIdx.x;
    float4 v = reinterpret_cast<const float4*>(src)[i];
    __nv_bfloat16 hv[4], lv[4];
    float f[4] = {v.x, v.y, v.z, v.w};
#pragma unroll
    for (int k = 0; k < 4; k++) {
        hv[k] = __float2bfloat16(f[k]);
        lv[k] = __float2bfloat16(f[k] - __bfloat162float(hv[k]));
    }
    reinterpret_cast<uint2*>(hi)[i] = *reinterpret_cast<uint2*>(hv);
    reinterpret_cast<uint2*>(lo)[i] = *reinterpret_cast<uint2*>(lv);
}

// w_down [E,H,D] -> w2t [E,D,H], split hi/lo
__global__ void __launch_bounds__(256) transpose_split_kernel(
    const float* __restrict__ w, __nv_bfloat16* __restrict__ th,
    __nv_bfloat16* __restrict__ tl) {
    __shared__ float tile[32][33];
    int e = blockIdx.z, hb = blockIdx.y, db = blockIdx.x;
    int tx = threadIdx.x, ty = threadIdx.y;  // 32 x 8
    const float* src = w + ((size_t)e * H_DIM + hb * 32) * D_DIM + db * 32;
#pragma unroll
    for (int j = 0; j < 32; j += 8)
        tile[ty + j][tx] = src[(size_t)(ty + j) * D_DIM + tx];
    __syncthreads();
    size_t ob = ((size_t)e * D_DIM + db * 32) * H_DIM + hb * 32;
#pragma unroll
    for (int j = 0; j < 32; j += 8) {
        float v = tile[tx][ty + j];
        __nv_bfloat16 hv = __float2bfloat16(v);
        size_t o = ob + (size_t)(ty + j) * H_DIM + tx;
        th[o] = hv;
        tl[o] = __float2bfloat16(v - __bfloat162float(hv));
    }
}

// ------------------------- silu + split kernel -----------------------------
// up_gate [16384, 2048] fp32 -> h = up*silu(gate) -> hh/hl [16384, 1024] bf16
__global__ void __launch_bounds__(256) silu_split_kernel() {
    size_t i = (size_t)blockIdx.x * blockDim.x + threadIdx.x;  // float4 index
    size_t row = i >> 8;          // 256 float4 per row (1024 cols)
    size_t c4 = (i & 255) << 2;   // column (float)
    const float* base = g_upgate + row * (2 * H_DIM);
    float4 up = *reinterpret_cast<const float4*>(base + c4);
    float4 gt = *reinterpret_cast<const float4*>(base + H_DIM + c4);
    float u[4] = {up.x, up.y, up.z, up.w};
    float g[4] = {gt.x, gt.y, gt.z, gt.w};
    __nv_bfloat16 hv[4], lv[4];
#pragma unroll
    for (int k = 0; k < 4; k++) {
        float a = u[k] * g[k] * (1.0f / (1.0f + __expf(-g[k])));
        hv[k] = __float2bfloat16(a);
        lv[k] = __float2bfloat16(a - __bfloat162float(hv[k]));
    }
    size_t o4 = (row * H_DIM + c4) >> 2;
    reinterpret_cast<uint2*>(g_hh)[o4] = *reinterpret_cast<uint2*>(hv);
    reinterpret_cast<uint2*>(g_hl)[o4] = *reinterpret_cast<uint2*>(lv);
}

// ------------------------- GEMM (3-term bf16, mma.sync) --------------------
// C[128x256 tile] = (Ah+Al)[128xK] x (Bh+Bl)[256xK]^T, terms hh + hl + lh.
// 8 warps as 2(m) x 4(n); warp tile 64x64; kchunk 64; 2-stage cp.async.
#define STAGE_A 16384            // one 128x64 bf16 tile (128B rows)
#define STAGE_B 32768            // one 256x64 bf16 tile
#define STAGE_BYTES (2 * STAGE_A + 2 * STAGE_B)  // Ah,Al,Bh,Bl = 96KB
#define GEMM_SMEM (2 * STAGE_BYTES)              // 192KB

__global__ void __launch_bounds__(256, 1) gemm3_kernel(
    const __nv_bfloat16* __restrict__ Ah, const __nv_bfloat16* __restrict__ Al,
    const __nv_bfloat16* __restrict__ Bh, const __nv_bfloat16* __restrict__ Bl,
    float* __restrict__ C, int K) {
    extern __shared__ char smem[];
    uint32_t sbase = smem_u32(smem);
    int tid = threadIdx.x, wid = tid >> 5, lane = tid & 31;
    int bx = blockIdx.x;
    int e = bx >> 6, rr = bx & 63, mt = rr >> 3, nt = rr & 7;

    const __nv_bfloat16* pAh = Ah + ((size_t)e * 1024 + mt * 128) * (size_t)K;
    const __nv_bfloat16* pAl = Al + ((size_t)e * 1024 + mt * 128) * (size_t)K;
    const __nv_bfloat16* pBh = Bh + ((size_t)e * 2048 + nt * 256) * (size_t)K;
    const __nv_bfloat16* pBl = Bl + ((size_t)e * 2048 + nt * 256) * (size_t)K;
    float* pC = C + ((size_t)e * 1024 + mt * 128) * 2048 + nt * 256;

    float acc[4][8][4];
#pragma unroll
    for (int a = 0; a < 4; a++)
#pragma unroll
        for (int b = 0; b < 8; b++)
#pragma unroll
            for (int c = 0; c < 4; c++) acc[a][b][c] = 0.0f;

    // ---- loader lane mapping: 16B chunk (t&7), row (t>>3) ----
    int lrow = tid >> 3, lc16 = tid & 7;

    // ---- ldmatrix lane address components (tile-local, pre-swizzle) ----
    int wm = wid & 1, wn = wid >> 1;
    uint32_t aLaneOff =
        (uint32_t)((wm * 64 + (lane & 15)) * 128 + ((lane >> 4) & 1) * 16);
    uint32_t bLaneOff =
        (uint32_t)((wn * 64 + (lane & 7) + ((lane >> 4) & 1) * 8) * 128 +
                   ((lane >> 3) & 1) * 16);

#define LOAD_STAGE(SB, KC)                                                   \
    do {                                                                     \
        size_t gk = (size_t)(KC)*64 + lc16 * 8;                              \
        _Pragma("unroll") for (int j = 0; j < 4; j++) {                      \
            int r = lrow + 32 * j;                                           \
            uint32_t so = (uint32_t)(r * 128 + lc16 * 16);                   \
            so ^= (so >> 3) & 0x70;                                          \
            cp16((SB) + so, pAh + (size_t)r * K + gk);                       \
            cp16((SB) + STAGE_A + so, pAl + (size_t)r * K + gk);             \
        }                                                                    \
        _Pragma("unroll") for (int j = 0; j < 8; j++) {                      \
            int r = lrow + 32 * j;                                           \
            uint32_t so = (uint32_t)(r * 128 + lc16 * 16);                   \
            so ^= (so >> 3) & 0x70;                                          \
            cp16((SB) + 2 * STAGE_A + so, pBh + (size_t)r * K + gk);         \
            cp16((SB) + 2 * STAGE_A + STAGE_B + so, pBl + (size_t)r * K + gk);\
        }                                                                    \
    } while (0)

    uint32_t sb0 = sbase, sb1 = sbase + STAGE_BYTES;
    int kiters = K >> 6;
    LOAD_STAGE(sb0, 0);
    cp_commit();
    LOAD_STAGE(sb1, 1);
    cp_commit();

#pragma unroll 1
    for (int kc = 0; kc < kiters; kc++) {
        uint32_t sb = (kc & 1) ? sb1 : sb0;
        cp_wait<1>();
        __syncthreads();

        uint32_t aT[2] = {sb, sb + STAGE_A};
        uint32_t bT[2] = {sb + 2 * STAGE_A, sb + 2 * STAGE_A + STAGE_B};
#pragma unroll
        for (int t = 0; t < 3; t++) {
            uint32_t at = aT[t == 2];  // terms: (Ah,Bh) (Ah,Bl) (Al,Bh)
            uint32_t bt = bT[t == 1];
#pragma unroll
            for (int k16 = 0; k16 < 4; k16++) {
                uint32_t a[4][4];
#pragma unroll
                for (int mf = 0; mf < 4; mf++) {
                    uint32_t off = aLaneOff + mf * 2048 + k16 * 32;
                    off ^= (off >> 3) & 0x70;
                    ldsm4(a[mf][0], a[mf][1], a[mf][2], a[mf][3], at + off);
                }
                uint32_t b[4][4];
#pragma unroll
                for (int np = 0; np < 4; np++) {
                    uint32_t off = bLaneOff + np * 2048 + k16 * 32;
                    off ^= (off >> 3) & 0x70;
                    ldsm4(b[np][0], b[np][1], b[np][2], b[np][3], bt + off);
                }
#pragma unroll
                for (int mf = 0; mf < 4; mf++)
#pragma unroll
                    for (int np = 0; np < 4; np++) {
                        mma16816(acc[mf][2 * np], a[mf][0], a[mf][1], a[mf][2],
                                 a[mf][3], b[np][0], b[np][1]);
                        mma16816(acc[mf][2 * np + 1], a[mf][0], a[mf][1],
                                 a[mf][2], a[mf][3], b[np][2], b[np][3]);
                    }
            }
        }
        __syncthreads();
        if (kc + 2 < kiters) LOAD_STAGE(sb, kc + 2);
        cp_commit();
    }

    // ---- epilogue: fp32 accum -> C ----
    int row0 = wm * 64 + (lane >> 2);
    int col0 = wn * 64 + (lane & 3) * 2;
#pragma unroll
    for (int mf = 0; mf < 4; mf++)
#pragma unroll
        for (int nf = 0; nf < 8; nf++) {
            int r = row0 + mf * 16, c = col0 + nf * 8;
            float2 v0 = {acc[mf][nf][0], acc[mf][nf][1]};
            float2 v1 = {acc[mf][nf][2], acc[mf][nf][3]};
            *reinterpret_cast<float2*>(pC + (size_t)r * 2048 + c) = v0;
            *reinterpret_cast<float2*>(pC + (size_t)(r + 8) * 2048 + c) = v1;
        }
#undef LOAD_STAGE
}

// ------------------------- launch ------------------------------------------
extern "C" void kernel_launch(void* const* d_in, const int* in_sizes, int n_in,
                              void* d_out, int out_size) {
    (void)in_sizes; (void)n_in; (void)out_size;
    const float* x = (const float*)d_in[0];
    const float* w1 = (const float*)d_in[1];
    const float* w2 = (const float*)d_in[2];
    float* out = (float*)d_out;

    cudaFuncSetAttribute(gemm3_kernel,
                         cudaFuncAttributeMaxDynamicSharedMemorySize, GEMM_SMEM);

    __nv_bfloat16 *xh, *xl, *w1h, *w1l, *w2th, *w2tl, *hh, *hl;
    float* upgate;
    cudaGetSymbolAddress((void**)&xh, g_xh);
    cudaGetSymbolAddress((void**)&xl, g_xl);
    cudaGetSymbolAddress((void**)&w1h, g_w1h);
    cudaGetSymbolAddress((void**)&w1l, g_w1l);
    cudaGetSymbolAddress((void**)&w2th, g_w2th);
    cudaGetSymbolAddress((void**)&w2tl, g_w2tl);
    cudaGetSymbolAddress((void**)&hh, g_hh);
    cudaGetSymbolAddress((void**)&hl, g_hl);
    cudaGetSymbolAddress((void**)&upgate, g_upgate);

    // pre-pass: bf16 hi/lo splits (+ w_down transpose)
    split_kernel<<<32768, 256>>>(x, xh, xl);    // 16384*2048 /4 /256
    split_kernel<<<65536, 256>>>(w1, w1h, w1l); // 16*2048*2048 /4 /256
    transpose_split_kernel<<<dim3(64, 32, 16), dim3(32, 8)>>>(w2, w2th, w2tl);

    // GEMM1: up_gate = x @ w1^T (per expert), fp32 out
    gemm3_kernel<<<N_EXP * 64, 256, GEMM_SMEM>>>(xh, xl, w1h, w1l, upgate,
                                                 D_DIM);
    // silu + split to bf16 hi/lo
    silu_split_kernel<<<16384, 256>>>();  // 16384*1024 /4 /256
    // GEMM2: out = h @ w2t^T (per expert), fp32 out
    gemm3_kernel<<<N_EXP * 64, 256, GEMM_SMEM>>>(hh, hl, w2th, w2tl, out,
                                                 H_DIM);
}

// round 4
// speedup vs baseline: 1.1842x; 1.1842x over previous
#include <cuda_runtime.h>
#include <cuda_bf16.h>
#include <stdint.h>

#define N_TOK 16384
#define D_DIM 2048
#define H_DIM 1024
#define N_EXP 16

// ------------------------- scratch (device globals; no allocs) -------------
__device__ __nv_bfloat16 g_xh[(size_t)N_TOK * D_DIM];
__device__ __nv_bfloat16 g_xl[(size_t)N_TOK * D_DIM];
__device__ __nv_bfloat16 g_w1h[(size_t)N_EXP * 2 * H_DIM * D_DIM];  // row-interleaved up/gate
__device__ __nv_bfloat16 g_w1l[(size_t)N_EXP * 2 * H_DIM * D_DIM];
__device__ __nv_bfloat16 g_w2th[(size_t)N_EXP * D_DIM * H_DIM];
__device__ __nv_bfloat16 g_w2tl[(size_t)N_EXP * D_DIM * H_DIM];
__device__ __nv_bfloat16 g_hh[(size_t)N_TOK * H_DIM];
__device__ __nv_bfloat16 g_hl[(size_t)N_TOK * H_DIM];

// ------------------------- PTX helpers (compute_103-legal only) ------------
__device__ __forceinline__ uint32_t smem_u32(const void* p) {
    uint32_t a;
    asm("{ .reg .u64 t; cvta.to.shared.u64 t, %1; cvt.u32.u64 %0, t; }"
        : "=r"(a) : "l"(p));
    return a;
}

__device__ __forceinline__ void cp16(uint32_t dst, const void* src) {
    asm volatile("cp.async.cg.shared.global [%0], [%1], 16;\n"
                 :: "r"(dst), "l"(src));
}
__device__ __forceinline__ void cp_commit() {
    asm volatile("cp.async.commit_group;\n" ::: "memory");
}
template <int NN>
__device__ __forceinline__ void cp_wait() {
    asm volatile("cp.async.wait_group %0;\n" :: "n"(NN) : "memory");
}

__device__ __forceinline__ void ldsm4(uint32_t* r, uint32_t addr) {
    asm volatile("ldmatrix.sync.aligned.m8n8.x4.shared.b16 {%0,%1,%2,%3}, [%4];"
                 : "=r"(r[0]), "=r"(r[1]), "=r"(r[2]), "=r"(r[3]) : "r"(addr));
}

__device__ __forceinline__ void mma16816(float* c, const uint32_t* a,
                                         uint32_t b0, uint32_t b1) {
    asm volatile(
        "mma.sync.aligned.m16n8k16.row.col.f32.bf16.bf16.f32 "
        "{%0,%1,%2,%3}, {%4,%5,%6,%7}, {%8,%9}, {%0,%1,%2,%3};"
        : "+f"(c[0]), "+f"(c[1]), "+f"(c[2]), "+f"(c[3])
        : "r"(a[0]), "r"(a[1]), "r"(a[2]), "r"(a[3]), "r"(b0), "r"(b1));
}

// ------------------------- pre-pass kernels --------------------------------
__global__ void __launch_bounds__(256) split_kernel(
    const float* __restrict__ src, __nv_bfloat16* __restrict__ hi,
    __nv_bfloat16* __restrict__ lo) {
    size_t i = (size_t)blockIdx.x * blockDim.x + threadIdx.x;
    float4 v = reinterpret_cast<const float4*>(src)[i];
    __nv_bfloat16 hv[4], lv[4];
    float f[4] = {v.x, v.y, v.z, v.w};
#pragma unroll
    for (int k = 0; k < 4; k++) {
        hv[k] = __float2bfloat16(f[k]);
        lv[k] = __float2bfloat16(f[k] - __bfloat162float(hv[k]));
    }
    reinterpret_cast<uint2*>(hi)[i] = *reinterpret_cast<uint2*>(hv);
    reinterpret_cast<uint2*>(lo)[i] = *reinterpret_cast<uint2*>(lv);
}

// w1 [E,2048,D] (up rows 0-1023, gate rows 1024-2047) -> interleaved rows:
// out row 2j = up_j, 2j+1 = gate_j; split hi/lo.
__global__ void __launch_bounds__(256) interleave_split_kernel(
    const float* __restrict__ w, __nv_bfloat16* __restrict__ hi,
    __nv_bfloat16* __restrict__ lo) {
    size_t i = (size_t)blockIdx.x * blockDim.x + threadIdx.x;  // float4 idx
    size_t row = i >> 9;            // D/4 = 512 float4 per row
    size_t c4 = (i & 511) << 2;
    int e = (int)(row >> 11);       // 2048 rows per expert
    int r = (int)(row & 2047);
    int nr = (r < 1024) ? (2 * r) : (2 * (r - 1024) + 1);
    float4 v = *reinterpret_cast<const float4*>(w + row * D_DIM + c4);
    __nv_bfloat16 hv[4], lv[4];
    float f[4] = {v.x, v.y, v.z, v.w};
#pragma unroll
    for (int k = 0; k < 4; k++) {
        hv[k] = __float2bfloat16(f[k]);
        lv[k] = __float2bfloat16(f[k] - __bfloat162float(hv[k]));
    }
    size_t o4 = (((size_t)e * 2048 + nr) * D_DIM + c4) >> 2;
    reinterpret_cast<uint2*>(hi)[o4] = *reinterpret_cast<uint2*>(hv);
    reinterpret_cast<uint2*>(lo)[o4] = *reinterpret_cast<uint2*>(lv);
}

// w_down [E,H,D] -> w2t [E,D,H], split hi/lo
__global__ void __launch_bounds__(256) transpose_split_kernel(
    const float* __restrict__ w, __nv_bfloat16* __restrict__ th,
    __nv_bfloat16* __restrict__ tl) {
    __shared__ float tile[32][33];
    int e = blockIdx.z, hb = blockIdx.y, db = blockIdx.x;
    int tx = threadIdx.x, ty = threadIdx.y;  // 32 x 8
    const float* src = w + ((size_t)e * H_DIM + hb * 32) * D_DIM + db * 32;
#pragma unroll
    for (int j = 0; j < 32; j += 8)
        tile[ty + j][tx] = src[(size_t)(ty + j) * D_DIM + tx];
    __syncthreads();
    size_t ob = ((size_t)e * D_DIM + db * 32) * H_DIM + hb * 32;
#pragma unroll
    for (int j = 0; j < 32; j += 8) {
        float v = tile[tx][ty + j];
        __nv_bfloat16 hv = __float2bfloat16(v);
        size_t o = ob + (size_t)(ty + j) * H_DIM + tx;
        th[o] = hv;
        tl[o] = __float2bfloat16(v - __bfloat162float(hv));
    }
}

// ------------------------- GEMM (3-term bf16, mma.sync) --------------------
// CTA tile 128(m) x 256(n), 16 warps as 4(m) x 4(n), warp tile 32x64.
// kchunk 64, 2-stage cp.async double buffer.
// Terms: Ah*Bh + Al*Bh + Ah*Bl.
#define STAGE_A 16384            // 128x64 bf16 (128B rows)
#define STAGE_B 32768            // 256x64 bf16
#define OFF_AL  16384
#define OFF_BH  32768
#define OFF_BL  65536
#define STAGE_BYTES 98304        // Ah,Al,Bh,Bl
#define GEMM_SMEM (2 * STAGE_BYTES)

template <bool FUSE_SILU>
__global__ void __launch_bounds__(512, 1) gemm3_kernel(
    const __nv_bfloat16* __restrict__ Ah, const __nv_bfloat16* __restrict__ Al,
    const __nv_bfloat16* __restrict__ Bh, const __nv_bfloat16* __restrict__ Bl,
    float* __restrict__ C, __nv_bfloat16* __restrict__ Hh,
    __nv_bfloat16* __restrict__ Hl, int K) {
    extern __shared__ char smem[];
    uint32_t sbase = smem_u32(smem);
    int tid = threadIdx.x, wid = tid >> 5, lane = tid & 31;
    int bx = blockIdx.x;
    int e = bx >> 6, rr = bx & 63, mt = rr >> 3, nt = rr & 7;

    const __nv_bfloat16* pAh = Ah + ((size_t)e * 1024 + mt * 128) * (size_t)K;
    const __nv_bfloat16* pAl = Al + ((size_t)e * 1024 + mt * 128) * (size_t)K;
    const __nv_bfloat16* pBh = Bh + ((size_t)e * 2048 + nt * 256) * (size_t)K;
    const __nv_bfloat16* pBl = Bl + ((size_t)e * 2048 + nt * 256) * (size_t)K;

    float acc[2][8][4];
#pragma unroll
    for (int a = 0; a < 2; a++)
#pragma unroll
        for (int b = 0; b < 8; b++)
#pragma unroll
            for (int c = 0; c < 4; c++) acc[a][b][c] = 0.0f;

    // loader mapping: 512 threads; 16B chunk (tid&7), row (tid>>3) in 0..63
    int lrow = tid >> 3, lc16 = tid & 7;
    int wm = wid & 3, wn = wid >> 2;

#define LOAD_STAGE(SB, KC)                                                    \
    do {                                                                      \
        size_t gk = (size_t)(KC)*64 + lc16 * 8;                               \
        _Pragma("unroll") for (int j = 0; j < 2; j++) {                       \
            int r = lrow + 64 * j;                                            \
            uint32_t so = (uint32_t)(r * 128 + lc16 * 16);                    \
            so ^= (so >> 3) & 0x70;                                           \
            cp16((SB) + so, pAh + (size_t)r * K + gk);                        \
            cp16((SB) + OFF_AL + so, pAl + (size_t)r * K + gk);               \
        }                                                                     \
        _Pragma("unroll") for (int j = 0; j < 4; j++) {                       \
            int r = lrow + 64 * j;                                            \
            uint32_t so = (uint32_t)(r * 128 + lc16 * 16);                    \
            so ^= (so >> 3) & 0x70;                                           \
            cp16((SB) + OFF_BH + so, pBh + (size_t)r * K + gk);               \
            cp16((SB) + OFF_BL + so, pBl + (size_t)r * K + gk);               \
        }                                                                     \
    } while (0)

    uint32_t sb0 = sbase, sb1 = sbase + STAGE_BYTES;
    int kiters = K >> 6;
    LOAD_STAGE(sb0, 0);
    cp_commit();
    LOAD_STAGE(sb1, 1);
    cp_commit();

    // ldmatrix lane-address bases (tile-local, pre-swizzle)
    uint32_t aBase =
        (uint32_t)((wm * 32 + (lane & 15)) * 128 + ((lane >> 4) & 1) * 16);
    uint32_t bBase =
        (uint32_t)((wn * 64 + (lane & 7) + ((lane >> 4) & 1) * 8) * 128 +
                   ((lane >> 3) & 1) * 16);

#pragma unroll 1
    for (int kc = 0; kc < kiters; kc++) {
        uint32_t sb = (kc & 1) ? sb1 : sb0;
        cp_wait<1>();
        __syncthreads();

#pragma unroll
        for (int k16 = 0; k16 < 4; k16++) {
            uint32_t ah[2][4], al[2][4], bb[4][4];
            uint32_t boff[4];
#pragma unroll
            for (int mf = 0; mf < 2; mf++) {
                uint32_t off = aBase + mf * 2048 + k16 * 32;
                off ^= (off >> 3) & 0x70;
                ldsm4(ah[mf], sb + off);
                ldsm4(al[mf], sb + OFF_AL + off);
            }
#pragma unroll
            for (int np = 0; np < 4; np++) {
                uint32_t off = bBase + np * 2048 + k16 * 32;
                off ^= (off >> 3) & 0x70;
                boff[np] = off;
                ldsm4(bb[np], sb + OFF_BH + off);
            }
            // hh + lh terms (share Bh fragments)
#pragma unroll
            for (int mf = 0; mf < 2; mf++)
#pragma unroll
                for (int np = 0; np < 4; np++) {
                    mma16816(acc[mf][2 * np], ah[mf], bb[np][0], bb[np][1]);
                    mma16816(acc[mf][2 * np + 1], ah[mf], bb[np][2], bb[np][3]);
                }
#pragma unroll
            for (int mf = 0; mf < 2; mf++)
#pragma unroll
                for (int np = 0; np < 4; np++) {
                    mma16816(acc[mf][2 * np], al[mf], bb[np][0], bb[np][1]);
                    mma16816(acc[mf][2 * np + 1], al[mf], bb[np][2], bb[np][3]);
                }
            // hl term (reload B as Bl)
#pragma unroll
            for (int np = 0; np < 4; np++) ldsm4(bb[np], sb + OFF_BL + boff[np]);
#pragma unroll
            for (int mf = 0; mf < 2; mf++)
#pragma unroll
                for (int np = 0; np < 4; np++) {
                    mma16816(acc[mf][2 * np], ah[mf], bb[np][0], bb[np][1]);
                    mma16816(acc[mf][2 * np + 1], ah[mf], bb[np][2], bb[np][3]);
                }
        }
        __syncthreads();
        if (kc + 2 < kiters) LOAD_STAGE(sb, kc + 2);
        cp_commit();
    }

    // ---- epilogue ----
    int row0 = wm * 32 + (lane >> 2);
    if (FUSE_SILU) {
        // interleaved cols: even = up, odd = gate. h = up * gate * sigmoid(gate)
        size_t grow0 = (size_t)e * 1024 + mt * 128 + row0;
        int hcol = nt * 128 + wn * 32 + (lane & 3);
#pragma unroll
        for (int mf = 0; mf < 2; mf++)
#pragma unroll
            for (int nf = 0; nf < 8; nf++) {
                size_t r = grow0 + mf * 16;
                int hc = hcol + nf * 4;
                float u0 = acc[mf][nf][0], g0 = acc[mf][nf][1];
                float u1 = acc[mf][nf][2], g1 = acc[mf][nf][3];
                float h0 = u0 * g0 * (1.0f / (1.0f + __expf(-g0)));
                float h1 = u1 * g1 * (1.0f / (1.0f + __expf(-g1)));
                __nv_bfloat16 h0h = __float2bfloat16(h0);
                __nv_bfloat16 h1h = __float2bfloat16(h1);
                Hh[r * H_DIM + hc] = h0h;
                Hl[r * H_DIM + hc] =
                    __float2bfloat16(h0 - __bfloat162float(h0h));
                Hh[(r + 8) * H_DIM + hc] = h1h;
                Hl[(r + 8) * H_DIM + hc] =
                    __float2bfloat16(h1 - __bfloat162float(h1h));
            }
    } else {
        float* pC = C + ((size_t)e * 1024 + mt * 128) * 2048 + nt * 256;
        int col0 = wn * 64 + (lane & 3) * 2;
#pragma unroll
        for (int mf = 0; mf < 2; mf++)
#pragma unroll
            for (int nf = 0; nf < 8; nf++) {
                int r = row0 + mf * 16, c = col0 + nf * 8;
                float2 v0 = {acc[mf][nf][0], acc[mf][nf][1]};
                float2 v1 = {acc[mf][nf][2], acc[mf][nf][3]};
                *reinterpret_cast<float2*>(pC + (size_t)r * 2048 + c) = v0;
                *reinterpret_cast<float2*>(pC + (size_t)(r + 8) * 2048 + c) = v1;
            }
    }
#undef LOAD_STAGE
}

// ------------------------- launch ------------------------------------------
extern "C" void kernel_launch(void* const* d_in, const int* in_sizes, int n_in,
                              void* d_out, int out_size) {
    (void)in_sizes; (void)n_in; (void)out_size;
    const float* x = (const float*)d_in[0];
    const float* w1 = (const float*)d_in[1];
    const float* w2 = (const float*)d_in[2];
    float* out = (float*)d_out;

    cudaFuncSetAttribute(gemm3_kernel<true>,
                         cudaFuncAttributeMaxDynamicSharedMemorySize, GEMM_SMEM);
    cudaFuncSetAttribute(gemm3_kernel<false>,
                         cudaFuncAttributeMaxDynamicSharedMemorySize, GEMM_SMEM);

    __nv_bfloat16 *xh, *xl, *w1h, *w1l, *w2th, *w2tl, *hh, *hl;
    cudaGetSymbolAddress((void**)&xh, g_xh);
    cudaGetSymbolAddress((void**)&xl, g_xl);
    cudaGetSymbolAddress((void**)&w1h, g_w1h);
    cudaGetSymbolAddress((void**)&w1l, g_w1l);
    cudaGetSymbolAddress((void**)&w2th, g_w2th);
    cudaGetSymbolAddress((void**)&w2tl, g_w2tl);
    cudaGetSymbolAddress((void**)&hh, g_hh);
    cudaGetSymbolAddress((void**)&hl, g_hl);

    // pre-pass: bf16 hi/lo splits (w1 row-interleaved; w2 transposed)
    split_kernel<<<32768, 256>>>(x, xh, xl);
    interleave_split_kernel<<<65536, 256>>>(w1, w1h, w1l);
    transpose_split_kernel<<<dim3(64, 32, 16), dim3(32, 8)>>>(w2, w2th, w2tl);

    // GEMM1: up/gate + fused silu -> h (bf16 hi/lo)
    gemm3_kernel<true><<<N_EXP * 64, 512, GEMM_SMEM>>>(
        xh, xl, w1h, w1l, nullptr, hh, hl, D_DIM);
    // GEMM2: out = h @ w2t^T
    gemm3_kernel<false><<<N_EXP * 64, 512, GEMM_SMEM>>>(
        hh, hl, w2th, w2tl, out, nullptr, nullptr, H_DIM);
}